// round 3
// baseline (speedup 1.0000x reference)
#include <cuda_runtime.h>
#include <cuda_fp16.h>
#include <mma.h>
#include <cstdint>

using namespace nvcuda;

// ---------------- problem constants ----------------
#define BROWS 4096
#define NOUT  4096
#define KTOT  4122
#define KPAD  4128            // multiple of 32

#define OFF_CD4 262
#define OFF_CD3 524
#define OFF_CD2 1042
#define OFF_CD1 2071

// ---------------- scratch (device globals; no allocs allowed) ----------------
__device__ float  g_cA1[(size_t)BROWS * 2051];
__device__ float  g_cA2[(size_t)BROWS * 1029];
__device__ float  g_cA3[(size_t)BROWS * 518];
__device__ __half g_C[(size_t)BROWS * KPAD];   // coeffs [M, K] row-major fp16
__device__ __half g_B[(size_t)KPAD * NOUT];    // stacked bases [K, N] row-major fp16

__constant__ float c_lo[8] = {
    -0.010597401784997278f,  0.032883011666982945f,  0.030841381835986965f,
    -0.18703481171888114f,  -0.02798376941698385f,   0.6308807679295904f,
     0.7148465705525415f,    0.23037781330885523f };
__constant__ float c_hi[8] = {
    -0.23037781330885523f,   0.7148465705525415f,   -0.6308807679295904f,
    -0.02798376941698385f,   0.18703481171888114f,   0.030841381835986965f,
    -0.032883011666982945f, -0.010597401784997278f };

// ---------------- DWT: one level, db4, pywt 'symmetric' ----------------
__global__ void dwt_level_kernel(const float* __restrict__ in, int Nin, int Nout,
                                 float* __restrict__ cA_f32,
                                 __half* __restrict__ C,
                                 int cA_col, int cD_col)
{
    int j   = blockIdx.x * blockDim.x + threadIdx.x;
    int row = blockIdx.y;
    if (j >= Nout) return;

    const float* a = in + (size_t)row * Nin;
    float sLo = 0.f, sHi = 0.f;
#pragma unroll
    for (int m = 0; m < 8; m++) {
        int i = 8 + 2 * j - m;
        int idx;
        if (i < 7)            idx = 6 - i;
        else if (i < Nin + 7) idx = i - 7;
        else                  idx = 2 * Nin + 6 - i;
        float v = __ldg(a + idx);
        sLo = fmaf(c_lo[m], v, sLo);
        sHi = fmaf(c_hi[m], v, sHi);
    }
    if (cA_f32)      cA_f32[(size_t)row * Nout + j] = sLo;
    if (cA_col >= 0) C[(size_t)row * KPAD + cA_col + j] = __float2half_rn(sLo);
    C[(size_t)row * KPAD + cD_col + j] = __float2half_rn(sHi);
}

// zero padding columns of C (cols KTOT..KPAD)
__global__ void zero_pad_kernel(__half* __restrict__ C)
{
    int row = blockIdx.x * blockDim.x + threadIdx.x;
    if (row >= BROWS) return;
    for (int c = KTOT; c < KPAD; c++)
        C[(size_t)row * KPAD + c] = __float2half_rn(0.f);
}

// ---------------- pack bases -> fp16 stacked [KPAD, 4096] row-major ----------------
__global__ void pack_b_kernel(const float* __restrict__ b0, const float* __restrict__ b1,
                              const float* __restrict__ b2, const float* __restrict__ b3,
                              const float* __restrict__ b4, __half* __restrict__ Bh)
{
    int n = (blockIdx.x * blockDim.x + threadIdx.x) * 8;
    int k = blockIdx.y;
    if (n >= NOUT) return;

    const float* src = nullptr; int r = 0;
    if      (k < OFF_CD4) { src = b0; r = k; }
    else if (k < OFF_CD3) { src = b1; r = k - OFF_CD4; }
    else if (k < OFF_CD2) { src = b2; r = k - OFF_CD3; }
    else if (k < OFF_CD1) { src = b3; r = k - OFF_CD2; }
    else if (k < KTOT)    { src = b4; r = k - OFF_CD1; }

    __half2 h[4];
    if (src) {
        const float4* p = (const float4*)(src + (size_t)r * NOUT + n);
        float4 v0 = p[0], v1 = p[1];
        h[0] = __floats2half2_rn(v0.x, v0.y);
        h[1] = __floats2half2_rn(v0.z, v0.w);
        h[2] = __floats2half2_rn(v1.x, v1.y);
        h[3] = __floats2half2_rn(v1.z, v1.w);
    } else {
        h[0] = h[1] = h[2] = h[3] = __half2half2(__float2half_rn(0.f));
    }
    *(int4*)(Bh + (size_t)k * NOUT + n) = *(int4*)h;
}

// ---------------- GEMM: [4096,4128] x [4128,4096] fp16 -> fp32 ----------------
// 128x256 CTA tile, BK=32, 256 threads (8 warps as 2m x 4n, 64x64 warp tiles),
// 4-stage cp.async pipeline, one __syncthreads per K-iter.
#define BM 128
#define BN 256
#define BK 32
#define STAGES 4
#define AS_LD 40          // halves per As row (32 + 8 pad), 80B (16B-aligned)
#define BS_LD 264         // halves per Bs row (256 + 8 pad), 528B (16B-aligned)
#define A_STAGE_H (BM * AS_LD)      // 5120 halves
#define B_STAGE_H (BK * BS_LD)      // 8448 halves
#define SMEM_H (STAGES * (A_STAGE_H + B_STAGE_H))
#define SMEM_BYTES (SMEM_H * 2)     // 108544

__device__ __forceinline__ void cp16(uint32_t saddr, const void* gaddr)
{
    asm volatile("cp.async.cg.shared.global [%0], [%1], 16;\n"
                 :: "r"(saddr), "l"(gaddr));
}

__global__ void __launch_bounds__(256, 1)
gemm_kernel(const __half* __restrict__ A, const __half* __restrict__ Bm,
            float* __restrict__ Cout)
{
    constexpr int K = KPAD, N = NOUT;
    extern __shared__ __half smem[];
    __half* AsBase = smem;
    __half* BsBase = smem + STAGES * A_STAGE_H;

    const int tid = threadIdx.x;
    const int wid = tid >> 5;
    const int wm  = wid >> 2;    // 0..1
    const int wn  = wid & 3;     // 0..3
    const int rowBase = blockIdx.y * BM;
    const int colBase = blockIdx.x * BN;

    // loader geometry
    // A tile: 128 rows x 32 halves = 512 int4; 2 per thread
    const int a_r0 = (tid + 0)   >> 2, a_c0 = ((tid + 0)   & 3) * 8;
    const int a_r1 = (tid + 256) >> 2, a_c1 = ((tid + 256) & 3) * 8;
    // B tile: 32 rows x 256 halves = 1024 int4; 4 per thread
    int b_r[4], b_c[4];
#pragma unroll
    for (int i = 0; i < 4; i++) {
        int idx = i * 256 + tid;
        b_r[i] = idx >> 5;
        b_c[i] = (idx & 31) * 8;
    }

    const __half* Ag = A + (size_t)rowBase * K;
    const __half* Bg = Bm + colBase;

    uint32_t sA = (uint32_t)__cvta_generic_to_shared(AsBase);
    uint32_t sB = (uint32_t)__cvta_generic_to_shared(BsBase);

    auto issue_stage = [&](int t, int slot) {
        const int kb = t * BK;
        uint32_t sa = sA + slot * A_STAGE_H * 2;
        uint32_t sb = sB + slot * B_STAGE_H * 2;
        cp16(sa + (a_r0 * AS_LD + a_c0) * 2, Ag + (size_t)a_r0 * K + kb + a_c0);
        cp16(sa + (a_r1 * AS_LD + a_c1) * 2, Ag + (size_t)a_r1 * K + kb + a_c1);
#pragma unroll
        for (int i = 0; i < 4; i++)
            cp16(sb + (b_r[i] * BS_LD + b_c[i]) * 2,
                 Bg + (size_t)(kb + b_r[i]) * N + b_c[i]);
        asm volatile("cp.async.commit_group;\n" ::: "memory");
    };

    wmma::fragment<wmma::accumulator, 16, 16, 16, float> acc[4][4];
#pragma unroll
    for (int i = 0; i < 4; i++)
#pragma unroll
        for (int j = 0; j < 4; j++) wmma::fill_fragment(acc[i][j], 0.0f);

    constexpr int NT = K / BK;     // 129
    issue_stage(0, 0);
    issue_stage(1, 1);
    issue_stage(2, 2);

    for (int t = 0; t < NT; t++) {
        asm volatile("cp.async.wait_group 2;\n" ::: "memory");
        __syncthreads();
        if (t + 3 < NT) issue_stage(t + 3, (t + 3) & (STAGES - 1));

        const int slot = t & (STAGES - 1);
        const __half* As = AsBase + slot * A_STAGE_H;
        const __half* Bs = BsBase + slot * B_STAGE_H;

#pragma unroll
        for (int kk = 0; kk < BK; kk += 16) {
            wmma::fragment<wmma::matrix_a, 16, 16, 16, __half, wmma::row_major> af[4];
            wmma::fragment<wmma::matrix_b, 16, 16, 16, __half, wmma::row_major> bf[4];
#pragma unroll
            for (int i = 0; i < 4; i++)
                wmma::load_matrix_sync(af[i], As + (wm * 64 + i * 16) * AS_LD + kk, AS_LD);
#pragma unroll
            for (int j = 0; j < 4; j++)
                wmma::load_matrix_sync(bf[j], Bs + kk * BS_LD + wn * 64 + j * 16, BS_LD);
#pragma unroll
            for (int i = 0; i < 4; i++)
#pragma unroll
                for (int j = 0; j < 4; j++)
                    wmma::mma_sync(acc[i][j], af[i], bf[j], acc[i][j]);
        }
    }

#pragma unroll
    for (int i = 0; i < 4; i++)
#pragma unroll
        for (int j = 0; j < 4; j++) {
            float* cp = Cout + (size_t)(rowBase + wm * 64 + i * 16) * N
                             + colBase + wn * 64 + j * 16;
            wmma::store_matrix_sync(cp, acc[i][j], N, wmma::mem_row_major);
        }
}

// ---------------- launch ----------------
extern "C" void kernel_launch(void* const* d_in, const int* in_sizes, int n_in,
                              void* d_out, int out_size)
{
    const float* x  = (const float*)d_in[0];
    const float* b0 = (const float*)d_in[1];
    const float* b1 = (const float*)d_in[2];
    const float* b2 = (const float*)d_in[3];
    const float* b3 = (const float*)d_in[4];
    const float* b4 = (const float*)d_in[5];
    float* out = (float*)d_out;

    float  *cA1, *cA2, *cA3;
    __half *Cm, *Bm;
    cudaGetSymbolAddress((void**)&cA1, g_cA1);
    cudaGetSymbolAddress((void**)&cA2, g_cA2);
    cudaGetSymbolAddress((void**)&cA3, g_cA3);
    cudaGetSymbolAddress((void**)&Cm,  g_C);
    cudaGetSymbolAddress((void**)&Bm,  g_B);

    cudaFuncSetAttribute(gemm_kernel,
                         cudaFuncAttributeMaxDynamicSharedMemorySize, SMEM_BYTES);

    // 4 DWT levels: 4096 -> 2051 -> 1029 -> 518 -> 262
    dwt_level_kernel<<<dim3((2051 + 255) / 256, BROWS), 256>>>(x,   4096, 2051, cA1, Cm, -1, OFF_CD1);
    dwt_level_kernel<<<dim3((1029 + 255) / 256, BROWS), 256>>>(cA1, 2051, 1029, cA2, Cm, -1, OFF_CD2);
    dwt_level_kernel<<<dim3(( 518 + 255) / 256, BROWS), 256>>>(cA2, 1029,  518, cA3, Cm, -1, OFF_CD3);
    dwt_level_kernel<<<dim3(( 262 + 255) / 256, BROWS), 256>>>(cA3,  518,  262, nullptr, Cm, 0, OFF_CD4);

    zero_pad_kernel<<<(BROWS + 255) / 256, 256>>>(Cm);
    pack_b_kernel<<<dim3(NOUT / (256 * 8), KPAD), 256>>>(b0, b1, b2, b3, b4, Bm);

    gemm_kernel<<<dim3(NOUT / BN, BROWS / BM), 256, SMEM_BYTES>>>(Cm, Bm, out);
}

// round 4
// speedup vs baseline: 1.7830x; 1.7830x over previous
#include <cuda_runtime.h>
#include <cuda_fp16.h>
#include <cstdint>

// ---------------- problem constants ----------------
#define BROWS 4096
#define NOUT  4096
#define KTOT  4122
#define KPAD  4160            // 130 * 32

#define OFF_CD4 262
#define OFF_CD3 524
#define OFF_CD2 1042
#define OFF_CD1 2071

// ---------------- scratch (device globals; no allocs allowed) ----------------
__device__ float  g_cA1[(size_t)BROWS * 2051];
__device__ float  g_cA2[(size_t)BROWS * 1029];
__device__ float  g_cA3[(size_t)BROWS * 518];
__device__ __half g_C[(size_t)BROWS * KPAD];   // coeffs [M, K] row-major fp16
__device__ __half g_B[(size_t)KPAD * NOUT];    // stacked bases [K, N] row-major fp16

__constant__ float c_lo[8] = {
    -0.010597401784997278f,  0.032883011666982945f,  0.030841381835986965f,
    -0.18703481171888114f,  -0.02798376941698385f,   0.6308807679295904f,
     0.7148465705525415f,    0.23037781330885523f };
__constant__ float c_hi[8] = {
    -0.23037781330885523f,   0.7148465705525415f,   -0.6308807679295904f,
    -0.02798376941698385f,   0.18703481171888114f,   0.030841381835986965f,
    -0.032883011666982945f, -0.010597401784997278f };

// ---------------- DWT: one level, db4, pywt 'symmetric' ----------------
__global__ void dwt_level_kernel(const float* __restrict__ in, int Nin, int Nout,
                                 float* __restrict__ cA_f32,
                                 __half* __restrict__ C,
                                 int cA_col, int cD_col)
{
    int j   = blockIdx.x * blockDim.x + threadIdx.x;
    int row = blockIdx.y;
    if (j >= Nout) return;

    const float* a = in + (size_t)row * Nin;
    float sLo = 0.f, sHi = 0.f;
#pragma unroll
    for (int m = 0; m < 8; m++) {
        int i = 8 + 2 * j - m;
        int idx;
        if (i < 7)            idx = 6 - i;
        else if (i < Nin + 7) idx = i - 7;
        else                  idx = 2 * Nin + 6 - i;
        float v = __ldg(a + idx);
        sLo = fmaf(c_lo[m], v, sLo);
        sHi = fmaf(c_hi[m], v, sHi);
    }
    if (cA_f32)      cA_f32[(size_t)row * Nout + j] = sLo;
    if (cA_col >= 0) C[(size_t)row * KPAD + cA_col + j] = __float2half_rn(sLo);
    C[(size_t)row * KPAD + cD_col + j] = __float2half_rn(sHi);
}

// zero padding columns of C (cols KTOT..KPAD)
__global__ void zero_pad_kernel(__half* __restrict__ C)
{
    int row = blockIdx.x * blockDim.x + threadIdx.x;
    if (row >= BROWS) return;
    for (int c = KTOT; c < KPAD; c++)
        C[(size_t)row * KPAD + c] = __float2half_rn(0.f);
}

// ---------------- pack bases -> fp16 stacked [KPAD, 4096] row-major ----------------
__global__ void pack_b_kernel(const float* __restrict__ b0, const float* __restrict__ b1,
                              const float* __restrict__ b2, const float* __restrict__ b3,
                              const float* __restrict__ b4, __half* __restrict__ Bh)
{
    int n = (blockIdx.x * blockDim.x + threadIdx.x) * 8;
    int k = blockIdx.y;
    if (n >= NOUT) return;

    const float* src = nullptr; int r = 0;
    if      (k < OFF_CD4) { src = b0; r = k; }
    else if (k < OFF_CD3) { src = b1; r = k - OFF_CD4; }
    else if (k < OFF_CD2) { src = b2; r = k - OFF_CD3; }
    else if (k < OFF_CD1) { src = b3; r = k - OFF_CD2; }
    else if (k < KTOT)    { src = b4; r = k - OFF_CD1; }

    __half2 h[4];
    if (src) {
        const float4* p = (const float4*)(src + (size_t)r * NOUT + n);
        float4 v0 = p[0], v1 = p[1];
        h[0] = __floats2half2_rn(v0.x, v0.y);
        h[1] = __floats2half2_rn(v0.z, v0.w);
        h[2] = __floats2half2_rn(v1.x, v1.y);
        h[3] = __floats2half2_rn(v1.z, v1.w);
    } else {
        h[0] = h[1] = h[2] = h[3] = __half2half2(__float2half_rn(0.f));
    }
    *(int4*)(Bh + (size_t)k * NOUT + n) = *(int4*)h;
}

// ---------------- GEMM: [4096,4160] x [4160,4096] fp16 -> fp32 ----------------
// mma.sync.m16n8k16 + ldmatrix + 4-stage cp.async.
// CTA tile 128x128, BK=32, 256 threads, 8 warps as 2(m) x 4(n), warp tile 64x32.
#define BM 128
#define BN 128
#define BK 32
#define STAGES 4
#define A_STAGE_BYTES 8192      // 128 x 32 halves
#define B_STAGE_BYTES 8192      // 32 x 128 halves
#define STAGE_BYTES   16384
#define SMEM_BYTES    (STAGES * STAGE_BYTES)   // 65536

// A smem swizzle: rows paired into 128B lines; chunkIdx = (r&1)*4 + (c>>3)
__device__ __forceinline__ uint32_t aswz(int r, int chunk) {
    return (uint32_t)(((r >> 1) * 128) + ((((r & 1) * 4 + chunk) ^ ((r >> 1) & 7)) << 4));
}
// B smem: 256B rows, xor low-3 chunk bits by row
__device__ __forceinline__ uint32_t bswz(int r, int chunk) {
    return (uint32_t)(r * 256 + (((chunk & 8) | ((chunk ^ r) & 7)) << 4));
}

__device__ __forceinline__ void cp16(uint32_t saddr, const void* gaddr) {
    asm volatile("cp.async.cg.shared.global [%0], [%1], 16;\n" :: "r"(saddr), "l"(gaddr));
}
__device__ __forceinline__ void ldsm4(uint32_t* r, uint32_t addr) {
    asm volatile("ldmatrix.sync.aligned.m8n8.x4.shared.b16 {%0,%1,%2,%3}, [%4];"
                 : "=r"(r[0]), "=r"(r[1]), "=r"(r[2]), "=r"(r[3]) : "r"(addr));
}
__device__ __forceinline__ void ldsm4t(uint32_t* r, uint32_t addr) {
    asm volatile("ldmatrix.sync.aligned.m8n8.x4.trans.shared.b16 {%0,%1,%2,%3}, [%4];"
                 : "=r"(r[0]), "=r"(r[1]), "=r"(r[2]), "=r"(r[3]) : "r"(addr));
}
__device__ __forceinline__ void mma16816(float* c, const uint32_t* a, uint32_t b0, uint32_t b1) {
    asm volatile("mma.sync.aligned.m16n8k16.row.col.f32.f16.f16.f32 "
                 "{%0,%1,%2,%3}, {%4,%5,%6,%7}, {%8,%9}, {%0,%1,%2,%3};"
                 : "+f"(c[0]), "+f"(c[1]), "+f"(c[2]), "+f"(c[3])
                 : "r"(a[0]), "r"(a[1]), "r"(a[2]), "r"(a[3]), "r"(b0), "r"(b1));
}

__global__ void __launch_bounds__(256)
gemm_kernel(const __half* __restrict__ A, const __half* __restrict__ Bm,
            float* __restrict__ Cout)
{
    constexpr int K = KPAD, N = NOUT;
    extern __shared__ char smem[];
    const uint32_t sbase = (uint32_t)__cvta_generic_to_shared(smem);

    const int tid = threadIdx.x;
    const int wid = tid >> 5, lid = tid & 31;
    const int wm  = wid & 1;        // 0..1 -> 64-row slice
    const int wn  = wid >> 1;       // 0..3 -> 32-col slice
    const int rowBase = blockIdx.y * BM;
    const int colBase = blockIdx.x * BN;

    const int l15 = lid & 15, lc = lid >> 4;

    // ---- loader geometry ----
    // A: 512 int4/stage -> 2 per thread
    const int aR0 = (tid + 0)   >> 2, aC0 = (tid + 0)   & 3;
    const int aR1 = (tid + 256) >> 2, aC1 = (tid + 256) & 3;
    const uint32_t aS0 = aswz(aR0, aC0), aS1 = aswz(aR1, aC1);
    // B: 512 int4/stage -> 2 per thread
    const int bR0 = (tid + 0)   >> 4, bC0 = (tid + 0)   & 15;
    const int bR1 = (tid + 256) >> 4, bC1 = (tid + 256) & 15;
    const uint32_t bS0 = bswz(bR0, bC0), bS1 = bswz(bR1, bC1);

    const __half* Ag = A + (size_t)rowBase * K;
    const __half* Bg = Bm + colBase;

    // ---- ldmatrix relative offsets ----
    uint32_t relA[4][2];
#pragma unroll
    for (int i = 0; i < 4; i++) {
        const int r   = wm * 64 + i * 16 + l15;
        const int bse = (r >> 1) * 128, key = (r & 1) * 4, x = (r >> 1) & 7;
#pragma unroll
        for (int ks = 0; ks < 2; ks++)
            relA[i][ks] = (uint32_t)(bse + (((key + ks * 2 + lc) ^ x) << 4));
    }
    uint32_t relB[2][2];
#pragma unroll
    for (int g = 0; g < 2; g++) {
        const int chunk = wn * 4 + g * 2 + lc;
#pragma unroll
        for (int ks = 0; ks < 2; ks++) {
            const int r = ks * 16 + l15;
            relB[g][ks] = (uint32_t)(r * 256 + (((chunk & 8) | ((chunk ^ r) & 7)) << 4));
        }
    }

    auto issue_stage = [&](int t) {
        const int kb = t * BK;
        const uint32_t sa = sbase + (t & (STAGES - 1)) * STAGE_BYTES;
        const uint32_t sb = sa + A_STAGE_BYTES;
        cp16(sa + aS0, Ag + (size_t)aR0 * K + kb + aC0 * 8);
        cp16(sa + aS1, Ag + (size_t)aR1 * K + kb + aC1 * 8);
        cp16(sb + bS0, Bg + (size_t)(kb + bR0) * N + bC0 * 8);
        cp16(sb + bS1, Bg + (size_t)(kb + bR1) * N + bC1 * 8);
        asm volatile("cp.async.commit_group;\n" ::: "memory");
    };

    float acc[4][4][4];
#pragma unroll
    for (int i = 0; i < 4; i++)
#pragma unroll
        for (int j = 0; j < 4; j++)
#pragma unroll
            for (int q = 0; q < 4; q++) acc[i][j][q] = 0.f;

    constexpr int NT = K / BK;    // 130
    issue_stage(0); issue_stage(1); issue_stage(2);

    for (int t = 0; t < NT; t++) {
        asm volatile("cp.async.wait_group 2;\n" ::: "memory");
        __syncthreads();
        if (t + 3 < NT) issue_stage(t + 3);

        const uint32_t sa = sbase + (t & (STAGES - 1)) * STAGE_BYTES;
        const uint32_t sb = sa + A_STAGE_BYTES;

#pragma unroll
        for (int ks = 0; ks < 2; ks++) {
            uint32_t af[4][4], bf[2][4];
#pragma unroll
            for (int i = 0; i < 4; i++) ldsm4(af[i], sa + relA[i][ks]);
#pragma unroll
            for (int g = 0; g < 2; g++) ldsm4t(bf[g], sb + relB[g][ks]);
#pragma unroll
            for (int i = 0; i < 4; i++)
#pragma unroll
                for (int j = 0; j < 4; j++)
                    mma16816(acc[i][j], af[i], bf[j >> 1][(j & 1) * 2],
                             bf[j >> 1][(j & 1) * 2 + 1]);
        }
    }

    // ---- epilogue: fragment -> gmem (float2 stores) ----
    const int er = lid >> 2, ec = (lid & 3) * 2;
#pragma unroll
    for (int i = 0; i < 4; i++) {
        const int row0 = rowBase + wm * 64 + i * 16 + er;
#pragma unroll
        for (int j = 0; j < 4; j++) {
            const int col = colBase + wn * 32 + j * 8 + ec;
            float* p0 = Cout + (size_t)row0 * N + col;
            float* p1 = Cout + (size_t)(row0 + 8) * N + col;
            p0[0] = acc[i][j][0]; p0[1] = acc[i][j][1];
            p1[0] = acc[i][j][2]; p1[1] = acc[i][j][3];
        }
    }
}

// ---------------- launch ----------------
extern "C" void kernel_launch(void* const* d_in, const int* in_sizes, int n_in,
                              void* d_out, int out_size)
{
    const float* x  = (const float*)d_in[0];
    const float* b0 = (const float*)d_in[1];
    const float* b1 = (const float*)d_in[2];
    const float* b2 = (const float*)d_in[3];
    const float* b3 = (const float*)d_in[4];
    const float* b4 = (const float*)d_in[5];
    float* out = (float*)d_out;

    float  *cA1, *cA2, *cA3;
    __half *Cm, *Bm;
    cudaGetSymbolAddress((void**)&cA1, g_cA1);
    cudaGetSymbolAddress((void**)&cA2, g_cA2);
    cudaGetSymbolAddress((void**)&cA3, g_cA3);
    cudaGetSymbolAddress((void**)&Cm,  g_C);
    cudaGetSymbolAddress((void**)&Bm,  g_B);

    cudaFuncSetAttribute(gemm_kernel,
                         cudaFuncAttributeMaxDynamicSharedMemorySize, SMEM_BYTES);

    // 4 DWT levels: 4096 -> 2051 -> 1029 -> 518 -> 262
    dwt_level_kernel<<<dim3((2051 + 255) / 256, BROWS), 256>>>(x,   4096, 2051, cA1, Cm, -1, OFF_CD1);
    dwt_level_kernel<<<dim3((1029 + 255) / 256, BROWS), 256>>>(cA1, 2051, 1029, cA2, Cm, -1, OFF_CD2);
    dwt_level_kernel<<<dim3(( 518 + 255) / 256, BROWS), 256>>>(cA2, 1029,  518, cA3, Cm, -1, OFF_CD3);
    dwt_level_kernel<<<dim3(( 262 + 255) / 256, BROWS), 256>>>(cA3,  518,  262, nullptr, Cm, 0, OFF_CD4);

    zero_pad_kernel<<<(BROWS + 255) / 256, 256>>>(Cm);
    pack_b_kernel<<<dim3(NOUT / (256 * 8), KPAD), 256>>>(b0, b1, b2, b3, b4, Bm);

    gemm_kernel<<<dim3(NOUT / BN, BROWS / BM), 256, SMEM_BYTES>>>(Cm, Bm, out);
}